// round 1
// baseline (speedup 1.0000x reference)
#include <cuda_runtime.h>
#include <cstring>
#include <cstdint>

#define THREADS 256
#define TM 128

typedef unsigned long long ull;

// ---- shared memory layout (floats) ----
#define SZ_A0   (36*128)
#define SZ_W0   (36*128)
#define SZ_H1   (128*128)
#define SZ_W1   (128*128)
#define OFF_A0  0
#define OFF_W0  (OFF_A0+SZ_A0)
#define OFF_H1  (OFF_W0+SZ_W0)
#define OFF_W1  (OFF_H1+SZ_H1)
#define OFF_B0  (OFF_W1+SZ_W1)
#define OFF_B1  (OFF_B0+128)
#define OFF_W2  (OFF_B1+128)
#define OFF_RED (OFF_W2+128)
#define SZ_RED  (128*17)
#define SMEM_FLOATS (OFF_RED+SZ_RED)
#define SMEM_BYTES  (SMEM_FLOATS*4)

__device__ __forceinline__ ull f2u(float x, float y){
    float2 f = make_float2(x, y); ull v; memcpy(&v, &f, 8); return v;
}
__device__ __forceinline__ float2 u2f(ull v){
    float2 f; memcpy(&f, &v, 8); return f;
}
// packed dual fp32 FMA (sm_103a): c.lo += a.lo*b.lo ; c.hi += a.hi*b.hi
__device__ __forceinline__ void ffma2(ull &c, ull a, ull b){
    asm("fma.rn.f32x2 %0, %1, %2, %0;" : "+l"(c) : "l"(a), "l"(b));
}

// Transposed-A smem layout with XOR swizzle on 4-float groups:
// logical [k][m] (m = point row, pitch 128 floats)
__device__ __forceinline__ int tidx(int k, int m){
    return k*128 + ((((m >> 2) ^ ((k >> 3) & 31)) & 31) << 2) + (m & 3);
}

// C[128m x 128n] += A^T(swizzled)[KK x 128m] * B[KK x 128n]
// thread (ty,tx): rows ty*8..ty*8+7 ; cols tx*4..tx*4+3 and 64+tx*4..64+tx*4+3
template<int KK>
__device__ __forceinline__ void gemm_acc(const float* __restrict__ As,
                                         const float* __restrict__ Bs,
                                         ull c[8][4], int ty, int tx){
    #pragma unroll 4
    for (int k = 0; k < KK; k++){
        const int fk = (k >> 3) & 31;
        float4 a0 = *(const float4*)&As[k*128 + ((((2*ty+0) ^ fk) & 31) << 2)];
        float4 a1 = *(const float4*)&As[k*128 + ((((2*ty+1) ^ fk) & 31) << 2)];
        ulonglong2 b0 = *(const ulonglong2*)&Bs[k*128 + tx*4];
        ulonglong2 b1 = *(const ulonglong2*)&Bs[k*128 + 64 + tx*4];
        float av[8] = {a0.x, a0.y, a0.z, a0.w, a1.x, a1.y, a1.z, a1.w};
        #pragma unroll
        for (int i = 0; i < 8; i++){
            ull aa = f2u(av[i], av[i]);
            ffma2(c[i][0], aa, b0.x);
            ffma2(c[i][1], aa, b0.y);
            ffma2(c[i][2], aa, b1.x);
            ffma2(c[i][3], aa, b1.y);
        }
    }
}

__device__ __forceinline__ int ncol(int tx, int j){
    return (j < 4) ? (tx*4 + j) : (64 + tx*4 + (j - 4));
}

__global__ void __launch_bounds__(THREADS, 1)
mlp_fused_kernel(const float* __restrict__ x,
                 const float* __restrict__ emb,
                 const float* __restrict__ et,
                 const float* __restrict__ W0,
                 const float* __restrict__ b0,
                 const float* __restrict__ W1,
                 const float* __restrict__ b1,
                 const float* __restrict__ W2,
                 const float* __restrict__ b2,
                 float* __restrict__ out,
                 int Nq, int E, int ntiles)
{
    extern __shared__ float smem[];
    float* A0s = smem + OFF_A0;
    float* W0s = smem + OFF_W0;
    float* H1s = smem + OFF_H1;
    float* W1s = smem + OFF_W1;
    float* b0s = smem + OFF_B0;
    float* b1s = smem + OFF_B1;
    float* w2s = smem + OFF_W2;
    float* red = smem + OFF_RED;

    const int t  = threadIdx.x;
    const int tx = t & 15;
    const int ty = t >> 4;

    // ---- stage weights once (persistent CTA) ----
    for (int i = t*4; i < 34*128; i += THREADS*4)
        *(float4*)&W0s[i] = *(const float4*)&W0[i];
    W0s[34*128 + t] = 0.0f;                       // zero K-pad rows 34,35 (256 floats)
    for (int i = t*4; i < 128*128; i += THREADS*4)
        *(float4*)&W1s[i] = *(const float4*)&W1[i];
    if (t < 128){ b0s[t] = b0[t]; b1s[t] = b1[t]; w2s[t] = W2[t]; }
    __syncthreads();

    float b0r[8], b1r[8], w2r[8];
    #pragma unroll
    for (int j = 0; j < 8; j++){
        int n = ncol(tx, j);
        b0r[j] = b0s[n]; b1r[j] = b1s[n]; w2r[j] = w2s[n];
    }
    const float b2v = b2[0];

    for (int tile = blockIdx.x; tile < ntiles; tile += gridDim.x){
        const int base = tile * TM;
        __syncthreads();   // previous tile fully consumed A0s/H1s/red

        // ---- build A0 (transposed, swizzled): rows k=0,1 = x ; 2..33 = lerped emb ; 34,35 = 0
        {
            const int m = t >> 1, half = t & 1;
            int gm = base + m; if (gm >= Nq) gm = Nq - 1;
            if (half == 0){
                float2 xv = *(const float2*)&x[2*gm];
                A0s[tidx(0, m)] = xv.x;
                A0s[tidx(1, m)] = xv.y;
            } else {
                A0s[tidx(34, m)] = 0.0f;
                A0s[tidx(35, m)] = 0.0f;
            }
            float ev = emb[gm];
            int e1 = (int)ev;
            int e2 = e1 + 1; if (e2 > E - 1) e2 = E - 1;
            float res = ev - (float)e1;
            const float4* r1 = (const float4*)&et[e1*32 + half*16];
            const float4* r2 = (const float4*)&et[e2*32 + half*16];
            #pragma unroll
            for (int q = 0; q < 4; q++){
                float4 u = r1[q], v = r2[q];
                int d = 2 + half*16 + q*4;
                A0s[tidx(d+0, m)] = u.x + (v.x - u.x) * res;
                A0s[tidx(d+1, m)] = u.y + (v.y - u.y) * res;
                A0s[tidx(d+2, m)] = u.z + (v.z - u.z) * res;
                A0s[tidx(d+3, m)] = u.w + (v.w - u.w) * res;
            }
        }
        __syncthreads();

        // ---- layer 1: [128,36] x [36,128] ----
        ull c[8][4];
        #pragma unroll
        for (int i = 0; i < 8; i++)
            #pragma unroll
            for (int q = 0; q < 4; q++) c[i][q] = 0ULL;
        gemm_acc<36>(A0s, W0s, c, ty, tx);

        // epilogue: +b0, clip, store transposed into H1s (vectorized over rows)
        #pragma unroll
        for (int j = 0; j < 8; j++){
            int n = ncol(tx, j);
            float vv[8];
            #pragma unroll
            for (int i = 0; i < 8; i++){
                float2 f = u2f(c[i][j >> 1]);
                float v = ((j & 1) ? f.y : f.x) + b0r[j];
                vv[i] = fminf(fmaxf(v, 0.0f), 1.0f);
            }
            *(float4*)&H1s[tidx(n, ty*8    )] = make_float4(vv[0], vv[1], vv[2], vv[3]);
            *(float4*)&H1s[tidx(n, ty*8 + 4)] = make_float4(vv[4], vv[5], vv[6], vv[7]);
        }
        __syncthreads();

        // ---- layer 2: [128,128] x [128,128] ----
        #pragma unroll
        for (int i = 0; i < 8; i++)
            #pragma unroll
            for (int q = 0; q < 4; q++) c[i][q] = 0ULL;
        gemm_acc<128>(H1s, W1s, c, ty, tx);

        // epilogue: +b1, clip, partial dot with W2
        float acc[8];
        #pragma unroll
        for (int i = 0; i < 8; i++) acc[i] = 0.0f;
        #pragma unroll
        for (int j = 0; j < 8; j++){
            #pragma unroll
            for (int i = 0; i < 8; i++){
                float2 f = u2f(c[i][j >> 1]);
                float v = ((j & 1) ? f.y : f.x) + b1r[j];
                v = fminf(fmaxf(v, 0.0f), 1.0f);
                acc[i] += v * w2r[j];
            }
        }
        #pragma unroll
        for (int i = 0; i < 8; i++) red[(ty*8 + i)*17 + tx] = acc[i];
        __syncthreads();

        // ---- layer 3 reduce + sigmoid + store ----
        if (t < TM){
            float z = b2v;
            #pragma unroll
            for (int q = 0; q < 16; q++) z += red[t*17 + q];
            float o = 1.0f / (1.0f + __expf(-z));
            int gm = base + t;
            if (gm < Nq) out[gm] = o;
        }
    }
}

extern "C" void kernel_launch(void* const* d_in, const int* in_sizes, int n_in,
                              void* d_out, int out_size)
{
    const float* x   = (const float*)d_in[0];
    const float* emb = (const float*)d_in[1];
    const float* et  = (const float*)d_in[2];
    const float* W0  = (const float*)d_in[3];
    const float* b0  = (const float*)d_in[4];
    const float* W1  = (const float*)d_in[5];
    const float* b1  = (const float*)d_in[6];
    const float* W2  = (const float*)d_in[7];
    const float* b2  = (const float*)d_in[8];
    float* out = (float*)d_out;

    const int Nq = in_sizes[1];          // embeddings: one per point
    const int E  = in_sizes[2] / 32;     // em_table rows
    const int ntiles = (Nq + TM - 1) / TM;

    cudaFuncSetAttribute(mlp_fused_kernel,
                         cudaFuncAttributeMaxDynamicSharedMemorySize, SMEM_BYTES);
    int sms = 148;
    cudaDeviceGetAttribute(&sms, cudaDevAttrMultiProcessorCount, 0);
    int grid = ntiles < sms ? ntiles : sms;

    mlp_fused_kernel<<<grid, THREADS, SMEM_BYTES>>>(
        x, emb, et, W0, b0, W1, b1, W2, b2, out, Nq, E, ntiles);
}

// round 3
// speedup vs baseline: 1.8979x; 1.8979x over previous
#include <cuda_runtime.h>
#include <cuda_bf16.h>
#include <cstdint>
#include <cstring>

#define THREADS 256
#define TM 128

#define SA0 104   // halves stride for A0 / W0  (208B, 16B-mult, 13 mod 8 = 5)
#define SA2 264   // halves stride for A2 / W1  (528B, 16B-mult, 33 mod 8 = 1)

// ---- smem byte layout ----
#define OFF_A0   0
#define OFF_W0   26624
#define OFF_A2   53248
#define OFF_W1   120832
#define OFF_B0S  188416
#define OFF_B1S  188928
#define OFF_W2S  189440
#define OFF_RED  189952
#define SMEM_BYTES 190976

__device__ __forceinline__ uint32_t s2u(const void* p){
    uint32_t a;
    asm("{ .reg .u64 t; cvta.to.shared.u64 t, %1; cvt.u32.u64 %0, t; }" : "=r"(a) : "l"(p));
    return a;
}

__device__ __forceinline__ void ldsm4(uint32_t r[4], uint32_t addr){
    asm volatile("ldmatrix.sync.aligned.m8n8.x4.shared.b16 {%0,%1,%2,%3}, [%4];"
                 : "=r"(r[0]), "=r"(r[1]), "=r"(r[2]), "=r"(r[3]) : "r"(addr));
}

__device__ __forceinline__ void mma_bf16(float c[4], const uint32_t a[4],
                                         uint32_t b0, uint32_t b1){
    asm volatile("mma.sync.aligned.m16n8k16.row.col.f32.bf16.bf16.f32 "
                 "{%0,%1,%2,%3}, {%4,%5,%6,%7}, {%8,%9}, {%0,%1,%2,%3};"
                 : "+f"(c[0]), "+f"(c[1]), "+f"(c[2]), "+f"(c[3])
                 : "r"(a[0]), "r"(a[1]), "r"(a[2]), "r"(a[3]), "r"(b0), "r"(b1));
}

__device__ __forceinline__ float clip01(float v){ return fminf(fmaxf(v, 0.f), 1.f); }

__device__ __forceinline__ uint32_t pack2(__nv_bfloat162 h){
    uint32_t u; memcpy(&u, &h, 4); return u;
}
__device__ __forceinline__ uint32_t bf2pack(float a, float b){
    return pack2(__floats2bfloat162_rn(a, b));
}

// 3-pass hi/lo GEMM: pass0 = A.hi x B.hi, pass1 = A.lo x B.hi, pass2 = A.hi x B.lo
template<int KS, int LOA, int LOB>
__device__ __forceinline__ void gemm3(uint32_t aB0, uint32_t aB1,
                                      const uint32_t bB[4], float c[2][8][4]){
    #pragma unroll
    for (int p = 0; p < 3; p++){
        const int ao = (p == 1) ? LOA : 0;
        const int bo = (p == 2) ? LOB : 0;
        #pragma unroll
        for (int ks = 0; ks < KS; ks++){
            const int ca = (ao + 16 * ks) * 2;
            const int cb = (bo + 16 * ks) * 2;
            uint32_t a0[4], a1[4], b[4][4];
            ldsm4(a0, aB0 + ca);
            ldsm4(a1, aB1 + ca);
            #pragma unroll
            for (int g = 0; g < 4; g++) ldsm4(b[g], bB[g] + cb);
            #pragma unroll
            for (int ni = 0; ni < 8; ni++){
                uint32_t b0v = b[ni >> 1][(ni & 1) * 2];
                uint32_t b1v = b[ni >> 1][(ni & 1) * 2 + 1];
                mma_bf16(c[0][ni], a0, b0v, b1v);
                mma_bf16(c[1][ni], a1, b0v, b1v);
            }
        }
    }
}

__global__ void __launch_bounds__(THREADS, 1)
mlp_hmma_kernel(const float* __restrict__ x,
                const float* __restrict__ emb,
                const float* __restrict__ et,
                const float* __restrict__ W0,
                const float* __restrict__ b0,
                const float* __restrict__ W1,
                const float* __restrict__ b1,
                const float* __restrict__ W2,
                const float* __restrict__ b2,
                float* __restrict__ out,
                int Nq, int E, int ntiles)
{
    extern __shared__ __align__(1024) char smem[];
    const uint32_t sb = s2u(smem);
    const int t = threadIdx.x;
    const int lane = t & 31, w = t >> 5;
    const int mw = w & 3, nw = w >> 2;

    // ---- zero A0 + W0 (covers K padding), load biases ----
    for (int i = t * 16; i < OFF_A2; i += THREADS * 16)
        *(float4*)(smem + i) = make_float4(0.f, 0.f, 0.f, 0.f);
    if (t < 128){
        ((float*)(smem + OFF_B0S))[t] = b0[t];
        ((float*)(smem + OFF_B1S))[t] = b1[t];
        ((float*)(smem + OFF_W2S))[t] = W2[t];
    }
    __syncthreads();

    // ---- stage W0^T hi/lo: W0s[n][k]=hi(W0[k][n]), [n][48+k]=lo ----
    for (int i = t; i < 34 * 128; i += THREADS){
        int k = i >> 7, n = i & 127;
        float v = W0[i];
        __nv_bfloat16 h = __float2bfloat16_rn(v);
        *(__nv_bfloat16*)(smem + OFF_W0 + (n * SA0 + k) * 2) = h;
        *(__nv_bfloat16*)(smem + OFF_W0 + (n * SA0 + 48 + k) * 2) =
            __float2bfloat16_rn(v - __bfloat162float(h));
    }
    // ---- stage W1^T hi/lo: hi col k, lo col 128+k ----
    for (int i = t; i < 128 * 128; i += THREADS){
        int k = i >> 7, n = i & 127;
        float v = W1[i];
        __nv_bfloat16 h = __float2bfloat16_rn(v);
        *(__nv_bfloat16*)(smem + OFF_W1 + (n * SA2 + k) * 2) = h;
        *(__nv_bfloat16*)(smem + OFF_W1 + (n * SA2 + 128 + k) * 2) =
            __float2bfloat16_rn(v - __bfloat162float(h));
    }
    __syncthreads();

    const float b2v = __ldg(b2);
    const float* b0s = (const float*)(smem + OFF_B0S);
    const float* b1s = (const float*)(smem + OFF_B1S);
    const float* w2s = (const float*)(smem + OFF_W2S);
    float* red = (float*)(smem + OFF_RED);

    // ---- ldmatrix lane bases ----
    const uint32_t a0B0 = sb + OFF_A0 + ((mw * 32 + (lane & 15)) * SA0) * 2 + (lane >> 4) * 16;
    const uint32_t a0B1 = a0B0 + 16 * SA0 * 2;
    const uint32_t a2B0 = sb + OFF_A2 + ((mw * 32 + (lane & 15)) * SA2) * 2 + (lane >> 4) * 16;
    const uint32_t a2B1 = a2B0 + 16 * SA2 * 2;
    const int nrow = (lane & 7) + ((lane >> 4) << 3);
    const int bko  = ((lane >> 3) & 1) * 16;
    uint32_t w0B[4], w1B[4];
    #pragma unroll
    for (int g = 0; g < 4; g++){
        w0B[g] = sb + OFF_W0 + ((nw * 64 + g * 16 + nrow) * SA0) * 2 + bko;
        w1B[g] = sb + OFF_W1 + ((nw * 64 + g * 16 + nrow) * SA2) * 2 + bko;
    }
    const int r0 = lane >> 2;
    const int cq = 2 * (lane & 3);

    for (int tile = blockIdx.x; tile < ntiles; tile += gridDim.x){
        const int base = tile * TM;
        __syncthreads();   // prior tile fully consumed A0s/A2s/red

        // ---- build A0 (bf16 hi cols 0-33, lo cols 48-81) ----
        {
            const int m = t >> 1, half = t & 1;
            int gm = base + m; if (gm >= Nq) gm = Nq - 1;
            float ev = __ldg(emb + gm);
            int e1 = (int)ev;
            int e2 = e1 + 1; if (e2 > E - 1) e2 = E - 1;
            float res = ev - (float)e1;
            char* A0c = smem + OFF_A0 + m * SA0 * 2;
            if (!half){
                float2 xv = *(const float2*)(x + 2 * gm);
                __nv_bfloat162 h = __floats2bfloat162_rn(xv.x, xv.y);
                *(uint32_t*)(A0c) = pack2(h);
                *(uint32_t*)(A0c + 96) = bf2pack(xv.x - __bfloat162float(h.x),
                                                 xv.y - __bfloat162float(h.y));
            }
            const float4* p1 = (const float4*)(et + e1 * 32 + half * 16);
            const float4* p2 = (const float4*)(et + e2 * 32 + half * 16);
            #pragma unroll
            for (int q = 0; q < 4; q++){
                float4 u = p1[q], v = p2[q];
                float f0 = u.x + (v.x - u.x) * res;
                float f1 = u.y + (v.y - u.y) * res;
                float f2 = u.z + (v.z - u.z) * res;
                float f3 = u.w + (v.w - u.w) * res;
                int c = 2 + half * 16 + q * 4;
                __nv_bfloat162 h0 = __floats2bfloat162_rn(f0, f1);
                __nv_bfloat162 h1 = __floats2bfloat162_rn(f2, f3);
                *(uint32_t*)(A0c + c * 2)       = pack2(h0);
                *(uint32_t*)(A0c + (c + 2) * 2) = pack2(h1);
                *(uint32_t*)(A0c + (48 + c) * 2) =
                    bf2pack(f0 - __bfloat162float(h0.x), f1 - __bfloat162float(h0.y));
                *(uint32_t*)(A0c + (50 + c) * 2) =
                    bf2pack(f2 - __bfloat162float(h1.x), f3 - __bfloat162float(h1.y));
            }
        }
        __syncthreads();

        // ---- layer 1: [128,48hi/lo] x [48,128] ----
        float c[2][8][4];
        #pragma unroll
        for (int mi = 0; mi < 2; mi++)
            #pragma unroll
            for (int ni = 0; ni < 8; ni++)
                #pragma unroll
                for (int q = 0; q < 4; q++) c[mi][ni][q] = 0.f;
        gemm3<3, 48, 48>(a0B0, a0B1, w0B, c);

        // ---- epilogue 1: +b0, clip, hi/lo split -> A2s ----
        #pragma unroll
        for (int mi = 0; mi < 2; mi++){
            char* rowp0 = smem + OFF_A2 + (mw * 32 + mi * 16 + r0) * SA2 * 2;
            char* rowp1 = rowp0 + 8 * SA2 * 2;
            #pragma unroll
            for (int ni = 0; ni < 8; ni++){
                int n = nw * 64 + ni * 8 + cq;
                float2 bb = *(const float2*)(b0s + n);
                float v00 = clip01(c[mi][ni][0] + bb.x);
                float v01 = clip01(c[mi][ni][1] + bb.y);
                float v10 = clip01(c[mi][ni][2] + bb.x);
                float v11 = clip01(c[mi][ni][3] + bb.y);
                __nv_bfloat162 h0 = __floats2bfloat162_rn(v00, v01);
                __nv_bfloat162 h1 = __floats2bfloat162_rn(v10, v11);
                *(uint32_t*)(rowp0 + n * 2)         = pack2(h0);
                *(uint32_t*)(rowp0 + (128 + n) * 2) =
                    bf2pack(v00 - __bfloat162float(h0.x), v01 - __bfloat162float(h0.y));
                *(uint32_t*)(rowp1 + n * 2)         = pack2(h1);
                *(uint32_t*)(rowp1 + (128 + n) * 2) =
                    bf2pack(v10 - __bfloat162float(h1.x), v11 - __bfloat162float(h1.y));
            }
        }
        __syncthreads();

        // ---- layer 2: [128,128hi/lo] x [128,128] ----
        #pragma unroll
        for (int mi = 0; mi < 2; mi++)
            #pragma unroll
            for (int ni = 0; ni < 8; ni++)
                #pragma unroll
                for (int q = 0; q < 4; q++) c[mi][ni][q] = 0.f;
        gemm3<8, 128, 128>(a2B0, a2B1, w1B, c);

        // ---- epilogue 2: +b1, clip, dot W2, reduce, sigmoid ----
        {
            float acc[2][2] = {{0.f, 0.f}, {0.f, 0.f}};
            #pragma unroll
            for (int mi = 0; mi < 2; mi++)
                #pragma unroll
                for (int ni = 0; ni < 8; ni++){
                    int n = nw * 64 + ni * 8 + cq;
                    float2 bb = *(const float2*)(b1s + n);
                    float2 ww = *(const float2*)(w2s + n);
                    acc[mi][0] = fmaf(clip01(c[mi][ni][0] + bb.x), ww.x,
                                 fmaf(clip01(c[mi][ni][1] + bb.y), ww.y, acc[mi][0]));
                    acc[mi][1] = fmaf(clip01(c[mi][ni][2] + bb.x), ww.x,
                                 fmaf(clip01(c[mi][ni][3] + bb.y), ww.y, acc[mi][1]));
                }
            #pragma unroll
            for (int mi = 0; mi < 2; mi++)
                #pragma unroll
                for (int hb = 0; hb < 2; hb++){
                    float v = acc[mi][hb];
                    v += __shfl_xor_sync(0xffffffffu, v, 1);
                    v += __shfl_xor_sync(0xffffffffu, v, 2);
                    if ((lane & 3) == 0)
                        red[(mw * 32 + mi * 16 + r0 + hb * 8) * 2 + nw] = v;
                }
        }
        __syncthreads();

        if (t < TM){
            float z = b2v + red[t * 2] + red[t * 2 + 1];
            float o = 1.f / (1.f + __expf(-z));
            int gm = base + t;
            if (gm < Nq) out[gm] = o;
        }
    }
}

extern "C" void kernel_launch(void* const* d_in, const int* in_sizes, int n_in,
                              void* d_out, int out_size)
{
    const float* x   = (const float*)d_in[0];
    const float* emb = (const float*)d_in[1];
    const float* et  = (const float*)d_in[2];
    const float* W0  = (const float*)d_in[3];
    const float* b0  = (const float*)d_in[4];
    const float* W1  = (const float*)d_in[5];
    const float* b1  = (const float*)d_in[6];
    const float* W2  = (const float*)d_in[7];
    const float* b2  = (const float*)d_in[8];
    float* out = (float*)d_out;

    const int Nq = in_sizes[1];
    const int E  = in_sizes[2] / 32;
    const int ntiles = (Nq + TM - 1) / TM;

    cudaFuncSetAttribute(mlp_hmma_kernel,
                         cudaFuncAttributeMaxDynamicSharedMemorySize, SMEM_BYTES);
    int sms = 148;
    cudaDeviceGetAttribute(&sms, cudaDevAttrMultiProcessorCount, 0);
    int grid = ntiles < sms ? ntiles : sms;

    mlp_hmma_kernel<<<grid, THREADS, SMEM_BYTES>>>(
        x, emb, et, W0, b0, W1, b1, W2, b2, out, Nq, E, ntiles);
}

// round 4
// speedup vs baseline: 2.9477x; 1.5532x over previous
#include <cuda_runtime.h>
#include <cuda_fp16.h>
#include <cstdint>
#include <cstring>

#define THREADS 256
#define TM 128

#define S0  56    // A0 stride (halves) = 112B : conflict-free ldmatrix
#define SW0 104   // W0 stride = 208B
#define S2  136   // A2 stride = 272B
#define SW1 264   // W1 stride = 528B

#define OFF_A0  0
#define OFF_W0  14336
#define OFF_A2  40960
#define OFF_W1  75776
#define OFF_B0S 143360
#define OFF_B1S 143872
#define OFF_W2S 144384
#define OFF_RED 144896
#define SMEM_BYTES 146432

__device__ __forceinline__ uint32_t s2u(const void* p){
    uint32_t a;
    asm("{ .reg .u64 t; cvta.to.shared.u64 t, %1; cvt.u32.u64 %0, t; }" : "=r"(a) : "l"(p));
    return a;
}
__device__ __forceinline__ void ldsm4(uint32_t r[4], uint32_t addr){
    asm volatile("ldmatrix.sync.aligned.m8n8.x4.shared.b16 {%0,%1,%2,%3}, [%4];"
                 : "=r"(r[0]), "=r"(r[1]), "=r"(r[2]), "=r"(r[3]) : "r"(addr));
}
__device__ __forceinline__ void stsm4(uint32_t addr, uint32_t r0, uint32_t r1,
                                      uint32_t r2, uint32_t r3){
    asm volatile("stmatrix.sync.aligned.m8n8.x4.shared.b16 [%0], {%1,%2,%3,%4};"
                 :: "r"(addr), "r"(r0), "r"(r1), "r"(r2), "r"(r3) : "memory");
}
__device__ __forceinline__ void mma_f16(float c[4], const uint32_t a[4],
                                        uint32_t b0, uint32_t b1){
    asm volatile("mma.sync.aligned.m16n8k16.row.col.f32.f16.f16.f32 "
                 "{%0,%1,%2,%3}, {%4,%5,%6,%7}, {%8,%9}, {%0,%1,%2,%3};"
                 : "+f"(c[0]), "+f"(c[1]), "+f"(c[2]), "+f"(c[3])
                 : "r"(a[0]), "r"(a[1]), "r"(a[2]), "r"(a[3]), "r"(b0), "r"(b1));
}
__device__ __forceinline__ float clip01(float v){ return fminf(fmaxf(v, 0.f), 1.f); }
__device__ __forceinline__ uint32_t pk2(float a, float b){
    __half2 h = __floats2half2_rn(a, b);
    uint32_t u; memcpy(&u, &h, 4); return u;
}

// 2-pass GEMM: pass0 = A x B.hi, pass1 = A x B.lo (A fragments reused)
template<int KS, int BOFF>
__device__ __forceinline__ void gemm2p(uint32_t aB0, uint32_t aB1,
                                       const uint32_t bB[4], float c[2][8][4]){
    #pragma unroll
    for (int ks = 0; ks < KS; ks++){
        uint32_t a0[4], a1[4];
        ldsm4(a0, aB0 + 32 * ks);
        ldsm4(a1, aB1 + 32 * ks);
        #pragma unroll
        for (int p = 0; p < 2; p++){
            const int cb = (p * BOFF + 16 * ks) * 2;
            uint32_t b[4][4];
            #pragma unroll
            for (int g = 0; g < 4; g++) ldsm4(b[g], bB[g] + cb);
            #pragma unroll
            for (int ni = 0; ni < 8; ni++){
                uint32_t b0v = b[ni >> 1][(ni & 1) * 2];
                uint32_t b1v = b[ni >> 1][(ni & 1) * 2 + 1];
                mma_f16(c[0][ni], a0, b0v, b1v);
                mma_f16(c[1][ni], a1, b0v, b1v);
            }
        }
    }
}

__global__ void __launch_bounds__(THREADS, 1)
mlp_hmma2_kernel(const float* __restrict__ x,
                 const float* __restrict__ emb,
                 const float* __restrict__ et,
                 const float* __restrict__ W0,
                 const float* __restrict__ b0,
                 const float* __restrict__ W1,
                 const float* __restrict__ b1,
                 const float* __restrict__ W2,
                 const float* __restrict__ b2,
                 float* __restrict__ out,
                 int Nq, int E, int ntiles)
{
    extern __shared__ __align__(1024) char smem[];
    const uint32_t sb = s2u(smem);
    const int t = threadIdx.x;
    const int lane = t & 31, w = t >> 5;
    const int mw = w & 3, nw = w >> 2;

    // ---- zero A0 + W0 regions (K padding), load biases ----
    for (int i = t * 16; i < OFF_A2; i += THREADS * 16)
        *(float4*)(smem + i) = make_float4(0.f, 0.f, 0.f, 0.f);
    if (t < 128){
        ((float*)(smem + OFF_B0S))[t] = b0[t];
        ((float*)(smem + OFF_B1S))[t] = b1[t];
        ((float*)(smem + OFF_W2S))[t] = W2[t];
    }
    __syncthreads();

    // ---- stage W0^T hi/lo fp16: hi at col k, lo at col 48+k ----
    for (int i = t; i < 34 * 128; i += THREADS){
        int k = i >> 7, n = i & 127;
        float v = W0[i];
        __half h = __float2half_rn(v);
        *(__half*)(smem + OFF_W0 + (n * SW0 + k) * 2) = h;
        *(__half*)(smem + OFF_W0 + (n * SW0 + 48 + k) * 2) =
            __float2half_rn(v - __half2float(h));
    }
    // ---- stage W1^T hi/lo fp16: hi col k, lo col 128+k ----
    for (int i = t; i < 128 * 128; i += THREADS){
        int k = i >> 7, n = i & 127;
        float v = W1[i];
        __half h = __float2half_rn(v);
        *(__half*)(smem + OFF_W1 + (n * SW1 + k) * 2) = h;
        *(__half*)(smem + OFF_W1 + (n * SW1 + 128 + k) * 2) =
            __float2half_rn(v - __half2float(h));
    }
    __syncthreads();

    const float b2v = __ldg(b2);
    const float* b0s = (const float*)(smem + OFF_B0S);
    const float* b1s = (const float*)(smem + OFF_B1S);
    const float* w2s = (const float*)(smem + OFF_W2S);
    float* red = (float*)(smem + OFF_RED);

    // ---- ldmatrix / stmatrix lane bases ----
    const uint32_t aB0 = sb + OFF_A0 + ((mw * 32 + (lane & 15)) * S0) * 2 + (lane >> 4) * 16;
    const uint32_t aB1 = aB0 + 16 * S0 * 2;
    const uint32_t a2B0 = sb + OFF_A2 + ((mw * 32 + (lane & 15)) * S2) * 2 + (lane >> 4) * 16;
    const uint32_t a2B1 = a2B0 + 16 * S2 * 2;
    const int nrow = (lane & 7) + ((lane >> 4) << 3);
    const int bko  = ((lane >> 3) & 1) * 16;
    uint32_t w0B[4], w1B[4];
    #pragma unroll
    for (int g = 0; g < 4; g++){
        w0B[g] = sb + OFF_W0 + ((nw * 64 + g * 16 + nrow) * SW0) * 2 + bko;
        w1B[g] = sb + OFF_W1 + ((nw * 64 + g * 16 + nrow) * SW1) * 2 + bko;
    }
    const uint32_t stA2 = sb + OFF_A2 + ((mw * 32 + lane) * S2) * 2 + nw * 128;
    const int r0 = lane >> 2;
    const int cq = 2 * (lane & 3);

    // ---- prefetch first tile's emb/x ----
    const int m = t >> 1, half = t & 1;
    float pf_ev; float2 pf_x = make_float2(0.f, 0.f);
    {
        int gm = blockIdx.x * TM + m; if (gm >= Nq) gm = Nq - 1;
        pf_ev = __ldg(emb + gm);
        if (!half) pf_x = *(const float2*)(x + 2 * gm);
    }

    for (int tile = blockIdx.x; tile < ntiles; tile += gridDim.x){
        const int base = tile * TM;
        __syncthreads();   // prior tile fully consumed A0/A2/red

        // ---- build A0 (fp16, cols 0..33; 34..55 stay zero) ----
        {
            float ev = pf_ev;
            int e1 = (int)ev;
            int e2 = e1 + 1; if (e2 > E - 1) e2 = E - 1;
            float res = ev - (float)e1;
            char* A0c = smem + OFF_A0 + m * S0 * 2;
            const float4* p1 = (const float4*)(et + e1 * 32 + half * 16);
            const float4* p2 = (const float4*)(et + e2 * 32 + half * 16);
            if (!half) *(uint32_t*)(A0c) = pk2(pf_x.x, pf_x.y);
            #pragma unroll
            for (int q = 0; q < 4; q++){
                float4 u = p1[q], v = p2[q];
                float f0 = u.x + (v.x - u.x) * res;
                float f1 = u.y + (v.y - u.y) * res;
                float f2 = u.z + (v.z - u.z) * res;
                float f3 = u.w + (v.w - u.w) * res;
                int c = 2 + half * 16 + q * 4;
                *(uint32_t*)(A0c + c * 2)       = pk2(f0, f1);
                *(uint32_t*)(A0c + (c + 2) * 2) = pk2(f2, f3);
            }
            // prefetch next tile's emb/x (completes during GEMMs)
            int tile2 = tile + gridDim.x;
            if (tile2 < ntiles){
                int gm2 = tile2 * TM + m; if (gm2 >= Nq) gm2 = Nq - 1;
                pf_ev = __ldg(emb + gm2);
                if (!half) pf_x = *(const float2*)(x + 2 * gm2);
            }
        }
        __syncthreads();

        // ---- layer 1: A0[128x48] x (W0.hi + W0.lo) ----
        float c[2][8][4];
        #pragma unroll
        for (int mi = 0; mi < 2; mi++)
            #pragma unroll
            for (int ni = 0; ni < 8; ni++)
                #pragma unroll
                for (int q = 0; q < 4; q++) c[mi][ni][q] = 0.f;
        gemm2p<3, 48>(aB0, aB1, w0B, c);

        // ---- epilogue 1: +b0, clip, fp16, stmatrix -> A2 ----
        #pragma unroll
        for (int ni = 0; ni < 8; ni++){
            int n = nw * 64 + ni * 8 + cq;
            float2 bb = *(const float2*)(b0s + n);
            uint32_t q0 = pk2(clip01(c[0][ni][0] + bb.x), clip01(c[0][ni][1] + bb.y));
            uint32_t q1 = pk2(clip01(c[0][ni][2] + bb.x), clip01(c[0][ni][3] + bb.y));
            uint32_t q2 = pk2(clip01(c[1][ni][0] + bb.x), clip01(c[1][ni][1] + bb.y));
            uint32_t q3 = pk2(clip01(c[1][ni][2] + bb.x), clip01(c[1][ni][3] + bb.y));
            stsm4(stA2 + ni * 16, q0, q1, q2, q3);
        }
        __syncthreads();

        // ---- layer 2: A2[128x128] x (W1.hi + W1.lo) ----
        #pragma unroll
        for (int mi = 0; mi < 2; mi++)
            #pragma unroll
            for (int ni = 0; ni < 8; ni++)
                #pragma unroll
                for (int q = 0; q < 4; q++) c[mi][ni][q] = 0.f;
        gemm2p<8, 128>(a2B0, a2B1, w1B, c);

        // ---- epilogue 2: +b1, clip, dot W2, reduce, sigmoid ----
        {
            float acc[2][2] = {{0.f, 0.f}, {0.f, 0.f}};
            #pragma unroll
            for (int mi = 0; mi < 2; mi++)
                #pragma unroll
                for (int ni = 0; ni < 8; ni++){
                    int n = nw * 64 + ni * 8 + cq;
                    float2 bb = *(const float2*)(b1s + n);
                    float2 ww = *(const float2*)(w2s + n);
                    acc[mi][0] = fmaf(clip01(c[mi][ni][0] + bb.x), ww.x,
                                 fmaf(clip01(c[mi][ni][1] + bb.y), ww.y, acc[mi][0]));
                    acc[mi][1] = fmaf(clip01(c[mi][ni][2] + bb.x), ww.x,
                                 fmaf(clip01(c[mi][ni][3] + bb.y), ww.y, acc[mi][1]));
                }
            #pragma unroll
            for (int mi = 0; mi < 2; mi++)
                #pragma unroll
                for (int hb = 0; hb < 2; hb++){
                    float v = acc[mi][hb];
                    v += __shfl_xor_sync(0xffffffffu, v, 1);
                    v += __shfl_xor_sync(0xffffffffu, v, 2);
                    if ((lane & 3) == 0)
                        red[(mw * 32 + mi * 16 + r0 + hb * 8) * 2 + nw] = v;
                }
        }
        __syncthreads();

        if (t < TM){
            float z = b2v + red[t * 2] + red[t * 2 + 1];
            float o = 1.f / (1.f + __expf(-z));
            int gm = base + t;
            if (gm < Nq) out[gm] = o;
        }
    }
}

extern "C" void kernel_launch(void* const* d_in, const int* in_sizes, int n_in,
                              void* d_out, int out_size)
{
    const float* x   = (const float*)d_in[0];
    const float* emb = (const float*)d_in[1];
    const float* et  = (const float*)d_in[2];
    const float* W0  = (const float*)d_in[3];
    const float* b0  = (const float*)d_in[4];
    const float* W1  = (const float*)d_in[5];
    const float* b1  = (const float*)d_in[6];
    const float* W2  = (const float*)d_in[7];
    const float* b2  = (const float*)d_in[8];
    float* out = (float*)d_out;

    const int Nq = in_sizes[1];
    const int E  = in_sizes[2] / 32;
    const int ntiles = (Nq + TM - 1) / TM;

    cudaFuncSetAttribute(mlp_hmma2_kernel,
                         cudaFuncAttributeMaxDynamicSharedMemorySize, SMEM_BYTES);
    int sms = 148;
    cudaDeviceGetAttribute(&sms, cudaDevAttrMultiProcessorCount, 0);
    int grid = ntiles < sms ? ntiles : sms;

    mlp_hmma2_kernel<<<grid, THREADS, SMEM_BYTES>>>(
        x, emb, et, W0, b0, W1, b1, W2, b2, out, Nq, E, ntiles);
}

// round 5
// speedup vs baseline: 4.8253x; 1.6370x over previous
#include <cuda_runtime.h>
#include <cuda_fp16.h>
#include <cstdint>
#include <cstring>

#define THREADS 256
#define TM 128

#define S0  56    // A0 / W0 stride (halves) = 112B
#define S2  136   // A2 / W1 stride (halves) = 272B

#define OFF_A0  0
#define OFF_W0  14336
#define OFF_A2  28672
#define OFF_W1  63488
#define OFF_B0S 98304
#define OFF_B1S 98816
#define OFF_W2S 99328
#define OFF_RED 99840
#define SMEM_BYTES 100864

__device__ __forceinline__ uint32_t s2u(const void* p){
    uint32_t a;
    asm("{ .reg .u64 t; cvta.to.shared.u64 t, %1; cvt.u32.u64 %0, t; }" : "=r"(a) : "l"(p));
    return a;
}
__device__ __forceinline__ void ldsm4(uint32_t r[4], uint32_t addr){
    asm volatile("ldmatrix.sync.aligned.m8n8.x4.shared.b16 {%0,%1,%2,%3}, [%4];"
                 : "=r"(r[0]), "=r"(r[1]), "=r"(r[2]), "=r"(r[3]) : "r"(addr));
}
__device__ __forceinline__ void stsm4(uint32_t addr, uint32_t r0, uint32_t r1,
                                      uint32_t r2, uint32_t r3){
    asm volatile("stmatrix.sync.aligned.m8n8.x4.shared.b16 [%0], {%1,%2,%3,%4};"
                 :: "r"(addr), "r"(r0), "r"(r1), "r"(r2), "r"(r3) : "memory");
}
__device__ __forceinline__ void mma_f16(float c[4], const uint32_t a[4],
                                        uint32_t b0, uint32_t b1){
    asm volatile("mma.sync.aligned.m16n8k16.row.col.f32.f16.f16.f32 "
                 "{%0,%1,%2,%3}, {%4,%5,%6,%7}, {%8,%9}, {%0,%1,%2,%3};"
                 : "+f"(c[0]), "+f"(c[1]), "+f"(c[2]), "+f"(c[3])
                 : "r"(a[0]), "r"(a[1]), "r"(a[2]), "r"(a[3]), "r"(b0), "r"(b1));
}
__device__ __forceinline__ float clip01(float v){ return fminf(fmaxf(v, 0.f), 1.f); }
__device__ __forceinline__ uint32_t pk2(float a, float b){
    __half2 h = __floats2half2_rn(a, b);
    uint32_t u; memcpy(&u, &h, 4); return u;
}

// single-pass fp16 GEMM
template<int KS>
__device__ __forceinline__ void gemm1p(uint32_t aB0, uint32_t aB1,
                                       const uint32_t bB[4], float c[2][8][4]){
    #pragma unroll
    for (int ks = 0; ks < KS; ks++){
        uint32_t a0[4], a1[4], b[4][4];
        ldsm4(a0, aB0 + 32 * ks);
        ldsm4(a1, aB1 + 32 * ks);
        #pragma unroll
        for (int g = 0; g < 4; g++) ldsm4(b[g], bB[g] + 32 * ks);
        #pragma unroll
        for (int ni = 0; ni < 8; ni++){
            uint32_t b0v = b[ni >> 1][(ni & 1) * 2];
            uint32_t b1v = b[ni >> 1][(ni & 1) * 2 + 1];
            mma_f16(c[0][ni], a0, b0v, b1v);
            mma_f16(c[1][ni], a1, b0v, b1v);
        }
    }
}

__global__ void __launch_bounds__(THREADS, 2)
mlp_hmma1_kernel(const float* __restrict__ x,
                 const float* __restrict__ emb,
                 const float* __restrict__ et,
                 const float* __restrict__ W0,
                 const float* __restrict__ b0,
                 const float* __restrict__ W1,
                 const float* __restrict__ b1,
                 const float* __restrict__ W2,
                 const float* __restrict__ b2,
                 float* __restrict__ out,
                 int Nq, int E, int ntiles)
{
    extern __shared__ __align__(1024) char smem[];
    const uint32_t sb = s2u(smem);
    const int t = threadIdx.x;
    const int lane = t & 31, w = t >> 5;
    const int mw = w & 3, nw = w >> 2;

    // ---- zero A0 + W0 regions (K padding), load biases ----
    for (int i = t * 16; i < OFF_A2; i += THREADS * 16)
        *(float4*)(smem + i) = make_float4(0.f, 0.f, 0.f, 0.f);
    if (t < 128){
        ((float*)(smem + OFF_B0S))[t] = b0[t];
        ((float*)(smem + OFF_B1S))[t] = b1[t];
        ((float*)(smem + OFF_W2S))[t] = W2[t];
    }
    __syncthreads();

    // ---- stage W0^T fp16: W0s[n][k] = fp16(W0[k][n]) ----
    for (int i = t; i < 34 * 128; i += THREADS){
        int k = i >> 7, n = i & 127;
        *(__half*)(smem + OFF_W0 + (n * S0 + k) * 2) = __float2half_rn(W0[i]);
    }
    // ---- stage W1^T fp16 ----
    for (int i = t; i < 128 * 128; i += THREADS){
        int k = i >> 7, n = i & 127;
        *(__half*)(smem + OFF_W1 + (n * S2 + k) * 2) = __float2half_rn(W1[i]);
    }
    __syncthreads();

    const float b2v = __ldg(b2);
    const float* b0s = (const float*)(smem + OFF_B0S);
    const float* b1s = (const float*)(smem + OFF_B1S);
    const float* w2s = (const float*)(smem + OFF_W2S);
    float* red = (float*)(smem + OFF_RED);

    // ---- ldmatrix / stmatrix lane bases ----
    const uint32_t aB0 = sb + OFF_A0 + ((mw * 32 + (lane & 15)) * S0) * 2 + (lane >> 4) * 16;
    const uint32_t aB1 = aB0 + 16 * S0 * 2;
    const uint32_t a2B0 = sb + OFF_A2 + ((mw * 32 + (lane & 15)) * S2) * 2 + (lane >> 4) * 16;
    const uint32_t a2B1 = a2B0 + 16 * S2 * 2;
    const int nrow = (lane & 7) + ((lane >> 4) << 3);
    const int bko  = ((lane >> 3) & 1) * 16;
    uint32_t w0B[4], w1B[4];
    #pragma unroll
    for (int g = 0; g < 4; g++){
        w0B[g] = sb + OFF_W0 + ((nw * 64 + g * 16 + nrow) * S0) * 2 + bko;
        w1B[g] = sb + OFF_W1 + ((nw * 64 + g * 16 + nrow) * S2) * 2 + bko;
    }
    const uint32_t stA2 = sb + OFF_A2 + ((mw * 32 + lane) * S2) * 2 + nw * 128;
    const int r0 = lane >> 2;
    const int cq = 2 * (lane & 3);

    // ---- prefetch first tile's emb/x ----
    const int m = t >> 1, half = t & 1;
    float pf_ev; float2 pf_x = make_float2(0.f, 0.f);
    {
        int gm = blockIdx.x * TM + m; if (gm >= Nq) gm = Nq - 1;
        pf_ev = __ldg(emb + gm);
        if (!half) pf_x = *(const float2*)(x + 2 * gm);
    }

    for (int tile = blockIdx.x; tile < ntiles; tile += gridDim.x){
        const int base = tile * TM;
        __syncthreads();   // prior tile fully consumed A0/A2/red

        // ---- build A0 (fp16, cols 0..33; 34..47 stay zero) ----
        {
            float ev = pf_ev;
            int e1 = (int)ev;
            int e2 = e1 + 1; if (e2 > E - 1) e2 = E - 1;
            float res = ev - (float)e1;
            char* A0c = smem + OFF_A0 + m * S0 * 2;
            const float4* p1 = (const float4*)(et + e1 * 32 + half * 16);
            const float4* p2 = (const float4*)(et + e2 * 32 + half * 16);
            if (!half) *(uint32_t*)(A0c) = pk2(pf_x.x, pf_x.y);
            #pragma unroll
            for (int q = 0; q < 4; q++){
                float4 u = p1[q], v = p2[q];
                float f0 = u.x + (v.x - u.x) * res;
                float f1 = u.y + (v.y - u.y) * res;
                float f2 = u.z + (v.z - u.z) * res;
                float f3 = u.w + (v.w - u.w) * res;
                int c = 2 + half * 16 + q * 4;
                *(uint32_t*)(A0c + c * 2)       = pk2(f0, f1);
                *(uint32_t*)(A0c + (c + 2) * 2) = pk2(f2, f3);
            }
            int tile2 = tile + gridDim.x;
            if (tile2 < ntiles){
                int gm2 = tile2 * TM + m; if (gm2 >= Nq) gm2 = Nq - 1;
                pf_ev = __ldg(emb + gm2);
                if (!half) pf_x = *(const float2*)(x + 2 * gm2);
            }
        }
        __syncthreads();

        // ---- layer 1: A0[128x48] x W0[48x128] ----
        float c[2][8][4];
        #pragma unroll
        for (int mi = 0; mi < 2; mi++)
            #pragma unroll
            for (int ni = 0; ni < 8; ni++)
                #pragma unroll
                for (int q = 0; q < 4; q++) c[mi][ni][q] = 0.f;
        gemm1p<3>(aB0, aB1, w0B, c);

        // ---- epilogue 1: +b0, clip, fp16, stmatrix -> A2 ----
        #pragma unroll
        for (int ni = 0; ni < 8; ni++){
            int n = nw * 64 + ni * 8 + cq;
            float2 bb = *(const float2*)(b0s + n);
            uint32_t q0 = pk2(clip01(c[0][ni][0] + bb.x), clip01(c[0][ni][1] + bb.y));
            uint32_t q1 = pk2(clip01(c[0][ni][2] + bb.x), clip01(c[0][ni][3] + bb.y));
            uint32_t q2 = pk2(clip01(c[1][ni][0] + bb.x), clip01(c[1][ni][1] + bb.y));
            uint32_t q3 = pk2(clip01(c[1][ni][2] + bb.x), clip01(c[1][ni][3] + bb.y));
            stsm4(stA2 + ni * 16, q0, q1, q2, q3);
        }
        __syncthreads();

        // ---- layer 2: A2[128x128] x W1[128x128] ----
        #pragma unroll
        for (int mi = 0; mi < 2; mi++)
            #pragma unroll
            for (int ni = 0; ni < 8; ni++)
                #pragma unroll
                for (int q = 0; q < 4; q++) c[mi][ni][q] = 0.f;
        gemm1p<8>(a2B0, a2B1, w1B, c);

        // ---- epilogue 2: +b1, clip, dot W2, reduce, sigmoid ----
        {
            float acc[2][2] = {{0.f, 0.f}, {0.f, 0.f}};
            #pragma unroll
            for (int mi = 0; mi < 2; mi++)
                #pragma unroll
                for (int ni = 0; ni < 8; ni++){
                    int n = nw * 64 + ni * 8 + cq;
                    float2 bb = *(const float2*)(b1s + n);
                    float2 ww = *(const float2*)(w2s + n);
                    acc[mi][0] = fmaf(clip01(c[mi][ni][0] + bb.x), ww.x,
                                 fmaf(clip01(c[mi][ni][1] + bb.y), ww.y, acc[mi][0]));
                    acc[mi][1] = fmaf(clip01(c[mi][ni][2] + bb.x), ww.x,
                                 fmaf(clip01(c[mi][ni][3] + bb.y), ww.y, acc[mi][1]));
                }
            #pragma unroll
            for (int mi = 0; mi < 2; mi++)
                #pragma unroll
                for (int hb = 0; hb < 2; hb++){
                    float v = acc[mi][hb];
                    v += __shfl_xor_sync(0xffffffffu, v, 1);
                    v += __shfl_xor_sync(0xffffffffu, v, 2);
                    if ((lane & 3) == 0)
                        red[(mw * 32 + mi * 16 + r0 + hb * 8) * 2 + nw] = v;
                }
        }
        __syncthreads();

        if (t < TM){
            float z = b2v + red[t * 2] + red[t * 2 + 1];
            float o = 1.f / (1.f + __expf(-z));
            int gm = base + t;
            if (gm < Nq) out[gm] = o;
        }
    }
}

extern "C" void kernel_launch(void* const* d_in, const int* in_sizes, int n_in,
                              void* d_out, int out_size)
{
    const float* x   = (const float*)d_in[0];
    const float* emb = (const float*)d_in[1];
    const float* et  = (const float*)d_in[2];
    const float* W0  = (const float*)d_in[3];
    const float* b0  = (const float*)d_in[4];
    const float* W1  = (const float*)d_in[5];
    const float* b1  = (const float*)d_in[6];
    const float* W2  = (const float*)d_in[7];
    const float* b2  = (const float*)d_in[8];
    float* out = (float*)d_out;

    const int Nq = in_sizes[1];
    const int E  = in_sizes[2] / 32;
    const int ntiles = (Nq + TM - 1) / TM;

    cudaFuncSetAttribute(mlp_hmma1_kernel,
                         cudaFuncAttributeMaxDynamicSharedMemorySize, SMEM_BYTES);
    int sms = 148;
    cudaDeviceGetAttribute(&sms, cudaDevAttrMultiProcessorCount, 0);
    int grid = 2 * sms;
    if (ntiles < grid) grid = ntiles;

    mlp_hmma1_kernel<<<grid, THREADS, SMEM_BYTES>>>(
        x, emb, et, W0, b0, W1, b1, W2, b2, out, Nq, E, ntiles);
}

// round 6
// speedup vs baseline: 4.8914x; 1.0137x over previous
#include <cuda_runtime.h>
#include <cuda_fp16.h>
#include <cstdint>
#include <cstring>

#define THREADS 512
#define TM 128

#define S0  56    // A0 / W0 stride (halves) = 112B
#define S2  136   // A2 / W1 stride (halves) = 272B

// ---- smem byte layout: shared weights + per-group activation blocks ----
#define OFF_W0   0                       // 14336
#define OFF_W1   14336                   // 34816
#define GBASE    49152
#define GSTRIDE  50176                   // A0 14336 + A2 34816 + red 1024
#define OFF_B0S  (GBASE + 2*GSTRIDE)     // 149504
#define OFF_B1S  (OFF_B0S + 512)
#define OFF_W2S  (OFF_B1S + 512)
#define SMEM_BYTES (OFF_W2S + 512)       // 151040

__device__ __forceinline__ uint32_t s2u(const void* p){
    uint32_t a;
    asm("{ .reg .u64 t; cvta.to.shared.u64 t, %1; cvt.u32.u64 %0, t; }" : "=r"(a) : "l"(p));
    return a;
}
__device__ __forceinline__ void ldsm4(uint32_t r[4], uint32_t addr){
    asm volatile("ldmatrix.sync.aligned.m8n8.x4.shared.b16 {%0,%1,%2,%3}, [%4];"
                 : "=r"(r[0]), "=r"(r[1]), "=r"(r[2]), "=r"(r[3]) : "r"(addr));
}
__device__ __forceinline__ void stsm4(uint32_t addr, uint32_t r0, uint32_t r1,
                                      uint32_t r2, uint32_t r3){
    asm volatile("stmatrix.sync.aligned.m8n8.x4.shared.b16 [%0], {%1,%2,%3,%4};"
                 :: "r"(addr), "r"(r0), "r"(r1), "r"(r2), "r"(r3) : "memory");
}
__device__ __forceinline__ void mma_f16(float c[4], const uint32_t a[4],
                                        uint32_t b0, uint32_t b1){
    asm volatile("mma.sync.aligned.m16n8k16.row.col.f32.f16.f16.f32 "
                 "{%0,%1,%2,%3}, {%4,%5,%6,%7}, {%8,%9}, {%0,%1,%2,%3};"
                 : "+f"(c[0]), "+f"(c[1]), "+f"(c[2]), "+f"(c[3])
                 : "r"(a[0]), "r"(a[1]), "r"(a[2]), "r"(a[3]), "r"(b0), "r"(b1));
}
__device__ __forceinline__ float clip01(float v){ return fminf(fmaxf(v, 0.f), 1.f); }
__device__ __forceinline__ uint32_t pk2(float a, float b){
    __half2 h = __floats2half2_rn(a, b);
    uint32_t u; memcpy(&u, &h, 4); return u;
}
// per-group named barrier (ids 1,2), 256 threads each
#define GBAR(g) asm volatile("bar.sync %0, 256;" :: "r"((g) + 1) : "memory")

// single-pass fp16 GEMM
template<int KS>
__device__ __forceinline__ void gemm1p(uint32_t aB0, uint32_t aB1,
                                       const uint32_t bB[4], float c[2][8][4]){
    #pragma unroll
    for (int ks = 0; ks < KS; ks++){
        uint32_t a0[4], a1[4], b[4][4];
        ldsm4(a0, aB0 + 32 * ks);
        ldsm4(a1, aB1 + 32 * ks);
        #pragma unroll
        for (int gg = 0; gg < 4; gg++) ldsm4(b[gg], bB[gg] + 32 * ks);
        #pragma unroll
        for (int ni = 0; ni < 8; ni++){
            uint32_t b0v = b[ni >> 1][(ni & 1) * 2];
            uint32_t b1v = b[ni >> 1][(ni & 1) * 2 + 1];
            mma_f16(c[0][ni], a0, b0v, b1v);
            mma_f16(c[1][ni], a1, b0v, b1v);
        }
    }
}

__global__ void __launch_bounds__(THREADS, 1)
mlp_pp_kernel(const float* __restrict__ x,
              const float* __restrict__ emb,
              const float* __restrict__ et,
              const float* __restrict__ W0,
              const float* __restrict__ b0,
              const float* __restrict__ W1,
              const float* __restrict__ b1,
              const float* __restrict__ W2,
              const float* __restrict__ b2,
              float* __restrict__ out,
              int Nq, int E, int ntiles)
{
    extern __shared__ __align__(1024) char smem[];
    const uint32_t sb = s2u(smem);
    const int tid = threadIdx.x;
    const int g   = tid >> 8;        // tile group 0/1
    const int t   = tid & 255;
    const int lane = t & 31, w = t >> 5;
    const int mw = w & 3, nw = w >> 2;

    const int a0off = GBASE + g * GSTRIDE;
    const int a2off = a0off + 14336;
    const int rdoff = a2off + 34816;

    // ---- zero W0 pad + both A0 buffers; load biases ----
    for (int i = tid * 16; i < 14336; i += THREADS * 16){
        *(float4*)(smem + OFF_W0 + i) = make_float4(0.f, 0.f, 0.f, 0.f);
        *(float4*)(smem + GBASE + i) = make_float4(0.f, 0.f, 0.f, 0.f);
        *(float4*)(smem + GBASE + GSTRIDE + i) = make_float4(0.f, 0.f, 0.f, 0.f);
    }
    if (tid < 128){
        ((float*)(smem + OFF_B0S))[tid] = b0[tid];
        ((float*)(smem + OFF_B1S))[tid] = b1[tid];
        ((float*)(smem + OFF_W2S))[tid] = W2[tid];
    }
    __syncthreads();

    // ---- stage W0^T / W1^T fp16 (shared by both groups) ----
    for (int i = tid; i < 34 * 128; i += THREADS){
        int k = i >> 7, n = i & 127;
        *(__half*)(smem + OFF_W0 + (n * S0 + k) * 2) = __float2half_rn(W0[i]);
    }
    for (int i = tid; i < 128 * 128; i += THREADS){
        int k = i >> 7, n = i & 127;
        *(__half*)(smem + OFF_W1 + (n * S2 + k) * 2) = __float2half_rn(W1[i]);
    }
    __syncthreads();

    const float b2v = __ldg(b2);
    const float* b0s = (const float*)(smem + OFF_B0S);
    const float* b1s = (const float*)(smem + OFF_B1S);
    const float* w2s = (const float*)(smem + OFF_W2S);
    float* red = (float*)(smem + rdoff);

    // ---- ldmatrix / stmatrix lane bases ----
    const uint32_t aB0 = sb + a0off + ((mw * 32 + (lane & 15)) * S0) * 2 + (lane >> 4) * 16;
    const uint32_t aB1 = aB0 + 16 * S0 * 2;
    const uint32_t a2B0 = sb + a2off + ((mw * 32 + (lane & 15)) * S2) * 2 + (lane >> 4) * 16;
    const uint32_t a2B1 = a2B0 + 16 * S2 * 2;
    const int nrow = (lane & 7) + ((lane >> 4) << 3);
    const int bko  = ((lane >> 3) & 1) * 16;
    uint32_t w0B[4], w1B[4];
    #pragma unroll
    for (int q = 0; q < 4; q++){
        w0B[q] = sb + OFF_W0 + ((nw * 64 + q * 16 + nrow) * S0) * 2 + bko;
        w1B[q] = sb + OFF_W1 + ((nw * 64 + q * 16 + nrow) * S2) * 2 + bko;
    }
    const uint32_t stA2 = sb + a2off + ((mw * 32 + lane) * S2) * 2 + nw * 128;
    const int r0 = lane >> 2;
    const int cq = 2 * (lane & 3);

    // ---- prefetch first tile's emb/x ----
    const int m = t >> 1, half = t & 1;
    const int tstep = 2 * gridDim.x;
    float pf_ev = 0.f; float2 pf_x = make_float2(0.f, 0.f);
    {
        int t0 = blockIdx.x * 2 + g;
        int gm = t0 * TM + m;
        if (gm >= Nq) gm = Nq - 1;
        pf_ev = __ldg(emb + gm);
        if (!half) pf_x = *(const float2*)(x + 2 * gm);
    }

    for (int tile = blockIdx.x * 2 + g; tile < ntiles; tile += tstep){
        const int base = tile * TM;
        GBAR(g);   // prior tile fully consumed A0/A2/red

        // ---- build A0 (fp16, cols 0..33; 34..47 stay zero) ----
        {
            float ev = pf_ev;
            int e1 = (int)ev;
            int e2 = e1 + 1; if (e2 > E - 1) e2 = E - 1;
            float res = ev - (float)e1;
            char* A0c = smem + a0off + m * S0 * 2;
            const float4* p1 = (const float4*)(et + e1 * 32 + half * 16);
            const float4* p2 = (const float4*)(et + e2 * 32 + half * 16);
            if (!half) *(uint32_t*)(A0c) = pk2(pf_x.x, pf_x.y);
            #pragma unroll
            for (int q = 0; q < 4; q++){
                float4 u = p1[q], v = p2[q];
                float f0 = u.x + (v.x - u.x) * res;
                float f1 = u.y + (v.y - u.y) * res;
                float f2 = u.z + (v.z - u.z) * res;
                float f3 = u.w + (v.w - u.w) * res;
                int c = 2 + half * 16 + q * 4;
                *(uint32_t*)(A0c + c * 2)       = pk2(f0, f1);
                *(uint32_t*)(A0c + (c + 2) * 2) = pk2(f2, f3);
            }
            int tile2 = tile + tstep;
            if (tile2 < ntiles){
                int gm2 = tile2 * TM + m; if (gm2 >= Nq) gm2 = Nq - 1;
                pf_ev = __ldg(emb + gm2);
                if (!half) pf_x = *(const float2*)(x + 2 * gm2);
            }
        }
        GBAR(g);

        // ---- layer 1: A0[128x48] x W0[48x128] ----
        float c[2][8][4];
        #pragma unroll
        for (int mi = 0; mi < 2; mi++)
            #pragma unroll
            for (int ni = 0; ni < 8; ni++)
                #pragma unroll
                for (int q = 0; q < 4; q++) c[mi][ni][q] = 0.f;
        gemm1p<3>(aB0, aB1, w0B, c);

        // ---- epilogue 1: +b0, clip, fp16, stmatrix -> A2 ----
        #pragma unroll
        for (int ni = 0; ni < 8; ni++){
            int n = nw * 64 + ni * 8 + cq;
            float2 bb = *(const float2*)(b0s + n);
            uint32_t q0 = pk2(clip01(c[0][ni][0] + bb.x), clip01(c[0][ni][1] + bb.y));
            uint32_t q1 = pk2(clip01(c[0][ni][2] + bb.x), clip01(c[0][ni][3] + bb.y));
            uint32_t q2 = pk2(clip01(c[1][ni][0] + bb.x), clip01(c[1][ni][1] + bb.y));
            uint32_t q3 = pk2(clip01(c[1][ni][2] + bb.x), clip01(c[1][ni][3] + bb.y));
            stsm4(stA2 + ni * 16, q0, q1, q2, q3);
        }
        GBAR(g);

        // ---- layer 2: A2[128x128] x W1[128x128] ----
        #pragma unroll
        for (int mi = 0; mi < 2; mi++)
            #pragma unroll
            for (int ni = 0; ni < 8; ni++)
                #pragma unroll
                for (int q = 0; q < 4; q++) c[mi][ni][q] = 0.f;
        gemm1p<8>(a2B0, a2B1, w1B, c);

        // ---- epilogue 2: +b1, clip, dot W2, reduce, sigmoid ----
        {
            float acc[2][2] = {{0.f, 0.f}, {0.f, 0.f}};
            #pragma unroll
            for (int mi = 0; mi < 2; mi++)
                #pragma unroll
                for (int ni = 0; ni < 8; ni++){
                    int n = nw * 64 + ni * 8 + cq;
                    float2 bb = *(const float2*)(b1s + n);
                    float2 ww = *(const float2*)(w2s + n);
                    acc[mi][0] = fmaf(clip01(c[mi][ni][0] + bb.x), ww.x,
                                 fmaf(clip01(c[mi][ni][1] + bb.y), ww.y, acc[mi][0]));
                    acc[mi][1] = fmaf(clip01(c[mi][ni][2] + bb.x), ww.x,
                                 fmaf(clip01(c[mi][ni][3] + bb.y), ww.y, acc[mi][1]));
                }
            #pragma unroll
            for (int mi = 0; mi < 2; mi++)
                #pragma unroll
                for (int hb = 0; hb < 2; hb++){
                    float v = acc[mi][hb];
                    v += __shfl_xor_sync(0xffffffffu, v, 1);
                    v += __shfl_xor_sync(0xffffffffu, v, 2);
                    if ((lane & 3) == 0)
                        red[(mw * 32 + mi * 16 + r0 + hb * 8) * 2 + nw] = v;
                }
        }
        GBAR(g);

        if (t < TM){
            float z = b2v + red[t * 2] + red[t * 2 + 1];
            float o = 1.f / (1.f + __expf(-z));
            int gm = base + t;
            if (gm < Nq) out[gm] = o;
        }
    }
}

extern "C" void kernel_launch(void* const* d_in, const int* in_sizes, int n_in,
                              void* d_out, int out_size)
{
    const float* x   = (const float*)d_in[0];
    const float* emb = (const float*)d_in[1];
    const float* et  = (const float*)d_in[2];
    const float* W0  = (const float*)d_in[3];
    const float* b0  = (const float*)d_in[4];
    const float* W1  = (const float*)d_in[5];
    const float* b1  = (const float*)d_in[6];
    const float* W2  = (const float*)d_in[7];
    const float* b2  = (const float*)d_in[8];
    float* out = (float*)d_out;

    const int Nq = in_sizes[1];
    const int E  = in_sizes[2] / 32;
    const int ntiles = (Nq + TM - 1) / TM;

    cudaFuncSetAttribute(mlp_pp_kernel,
                         cudaFuncAttributeMaxDynamicSharedMemorySize, SMEM_BYTES);
    int sms = 148;
    cudaDeviceGetAttribute(&sms, cudaDevAttrMultiProcessorCount, 0);
    int grid = (ntiles + 1) / 2;
    if (grid > sms) grid = sms;

    mlp_pp_kernel<<<grid, THREADS, SMEM_BYTES>>>(
        x, emb, et, W0, b0, W1, b1, W2, b2, out, Nq, E, ntiles);
}